// round 2
// baseline (speedup 1.0000x reference)
#include <cuda_runtime.h>

// NeighborlistVerletNsq: all-pairs PBC displacement + cutoff mask.
// Output layout (float32, element offsets, P = N(N-1)/2 unique pairs):
//   [0P..1P)  i_pairs        [1P..2P) j_pairs
//   [2P..3P)  j_pairs        [3P..4P) i_pairs
//   [4P..5P)  d_m            [5P..6P) d_m
//   [6P..9P)  r_m (row-major [P,3])
//   [9P..12P) -r_m
//   [12P..13P) mask          [13P..14P) mask
//
// i/j are NOT read from DRAM: triu_indices is reconstructed analytically from
// the flat pair index (inverse triangular number), saving 67 MB of reads.

__device__ __forceinline__ float wrap_pbc(float x, float L, float h) {
    // matches jnp.remainder(x + h, L) - h  (floor-mod), L > 0
    float t = x + h;
    float m = fmodf(t, L);       // exact trunc-mod, sign of t
    if (m < 0.0f) m += L;        // floor-mod fixup
    return m - h;
}

// row start offset of row i in the triu(k=1) enumeration: S(i) = i*(2N-1-i)/2
__device__ __forceinline__ int row_start(int i, int N) {
    return (i * (2 * N - 1 - i)) >> 1;
}

__global__ void __launch_bounds__(256)
nlist_kernel(const float* __restrict__ pos,
             const float* __restrict__ box,
             float*       __restrict__ out,
             int P, int N)
{
    const int t  = blockIdx.x * blockDim.x + threadIdx.x;
    const int p0 = t * 4;
    if (p0 >= P) return;

    const float Lx = __ldg(box + 0);
    const float Ly = __ldg(box + 4);
    const float Lz = __ldg(box + 8);
    const float hx = 0.5f * Lx, hy = 0.5f * Ly, hz = 0.5f * Lz;
    const float CUTOFF = 0.5f;

    const size_t Ps = (size_t)P;

    // ---- recover (i, j) for flat index p0 ----
    // Solve i^2 - (2N-1) i + 2p = 0 -> i = ((2N-1) - sqrt((2N-1)^2 - 8p)) / 2
    const long long A = 2LL * N - 1;
    const long long disc = A * A - 8LL * (long long)p0;   // > 0 always
    int i = (int)(((double)A - sqrt((double)disc)) * 0.5);
    if (i < 0) i = 0;
    if (i > N - 2) i = N - 2;
    // exact fixup (at most one step each way)
    while (i < N - 2 && row_start(i + 1, N) <= p0) ++i;
    while (i > 0 && row_start(i, N) > p0) --i;
    int rem = p0 - row_start(i, N);   // offset within row i; j = i+1+rem

    int is[4], js[4];
    int nk = (p0 + 3 < P) ? 4 : (P - p0);
    #pragma unroll
    for (int k = 0; k < 4; k++) {
        if (k < nk) {
            is[k] = i;
            js[k] = i + 1 + rem;
            ++rem;
            if (rem >= N - 1 - i) { rem = 0; ++i; }
        } else {
            is[k] = 0; js[k] = 1;  // dummy (never stored)
        }
    }

    float rx[4], ry[4], rz[4], dd[4], mk[4];
    #pragma unroll
    for (int k = 0; k < 4; k++) {
        const float* pi = pos + 3 * (size_t)is[k];
        const float* pj = pos + 3 * (size_t)js[k];
        float x = __ldg(pi + 0) - __ldg(pj + 0);
        float y = __ldg(pi + 1) - __ldg(pj + 1);
        float z = __ldg(pi + 2) - __ldg(pj + 2);
        x = wrap_pbc(x, Lx, hx);
        y = wrap_pbc(y, Ly, hy);
        z = wrap_pbc(z, Lz, hz);
        float d = sqrtf(x * x + y * y + z * z);
        bool m = (d <= CUTOFF);
        rx[k] = m ? x : 0.0f;
        ry[k] = m ? y : 0.0f;
        rz[k] = m ? z : 0.0f;
        dd[k] = m ? d : 0.0f;
        mk[k] = m ? 1.0f : 0.0f;
    }

    if (nk == 4) {
        // ---- vector path: 4 pairs per thread, all 16B stores ----
        const float4 fi = make_float4((float)is[0], (float)is[1], (float)is[2], (float)is[3]);
        const float4 fj = make_float4((float)js[0], (float)js[1], (float)js[2], (float)js[3]);
        const float4 fd = make_float4(dd[0], dd[1], dd[2], dd[3]);
        const float4 fm = make_float4(mk[0], mk[1], mk[2], mk[3]);

        __stcs((float4*)(out +  0 * Ps + p0), fi);
        __stcs((float4*)(out +  1 * Ps + p0), fj);
        __stcs((float4*)(out +  2 * Ps + p0), fj);
        __stcs((float4*)(out +  3 * Ps + p0), fi);
        __stcs((float4*)(out +  4 * Ps + p0), fd);
        __stcs((float4*)(out +  5 * Ps + p0), fd);

        float* rpos = out + 6 * Ps + 3 * (size_t)p0;
        __stcs((float4*)(rpos + 0), make_float4(rx[0], ry[0], rz[0], rx[1]));
        __stcs((float4*)(rpos + 4), make_float4(ry[1], rz[1], rx[2], ry[2]));
        __stcs((float4*)(rpos + 8), make_float4(rz[2], rx[3], ry[3], rz[3]));

        float* rneg = out + 9 * Ps + 3 * (size_t)p0;
        __stcs((float4*)(rneg + 0), make_float4(-rx[0], -ry[0], -rz[0], -rx[1]));
        __stcs((float4*)(rneg + 4), make_float4(-ry[1], -rz[1], -rx[2], -ry[2]));
        __stcs((float4*)(rneg + 8), make_float4(-rz[2], -rx[3], -ry[3], -rz[3]));

        __stcs((float4*)(out + 12 * Ps + p0), fm);
        __stcs((float4*)(out + 13 * Ps + p0), fm);
    } else {
        // ---- scalar tail ----
        for (int k = 0; k < nk; k++) {
            int p = p0 + k;
            out[ 0 * Ps + p] = (float)is[k];
            out[ 1 * Ps + p] = (float)js[k];
            out[ 2 * Ps + p] = (float)js[k];
            out[ 3 * Ps + p] = (float)is[k];
            out[ 4 * Ps + p] = dd[k];
            out[ 5 * Ps + p] = dd[k];
            out[ 6 * Ps + 3 * (size_t)p + 0] =  rx[k];
            out[ 6 * Ps + 3 * (size_t)p + 1] =  ry[k];
            out[ 6 * Ps + 3 * (size_t)p + 2] =  rz[k];
            out[ 9 * Ps + 3 * (size_t)p + 0] = -rx[k];
            out[ 9 * Ps + 3 * (size_t)p + 1] = -ry[k];
            out[ 9 * Ps + 3 * (size_t)p + 2] = -rz[k];
            out[12 * Ps + p] = mk[k];
            out[13 * Ps + p] = mk[k];
        }
    }
}

extern "C" void kernel_launch(void* const* d_in, const int* in_sizes, int n_in,
                              void* d_out, int out_size)
{
    const float* pos = (const float*)d_in[0];   // [N,3] float32
    const float* box = (const float*)d_in[1];   // [3,3] float32
    // d_in[2], d_in[3] = i_pairs, j_pairs — reconstructed analytically instead
    float* out = (float*)d_out;

    const int P = in_sizes[2];
    const int N = in_sizes[0] / 3;
    const int nthreads = (P + 3) / 4;
    const int block = 256;
    const int grid = (nthreads + block - 1) / block;
    nlist_kernel<<<grid, block>>>(pos, box, out, P, N);
}

// round 3
// speedup vs baseline: 1.0729x; 1.0729x over previous
#include <cuda_runtime.h>
#include <cstdint>

// NeighborlistVerletNsq: all-pairs PBC displacement + cutoff mask.
// Output layout (float32, element offsets, P = N(N-1)/2 unique pairs):
//   [0P..1P)  i   [1P..2P) j   [2P..3P) j   [3P..4P) i
//   [4P..5P)  d   [5P..6P) d
//   [6P..9P)  r (row-major [P,3])   [9P..12P) -r
//   [12P..13P) mask  [13P..14P) mask
//
// Strategy: block computes 1024 consecutive pairs into SMEM (unique regions
// only), then drains to GMEM via cp.async.bulk (TMA engine) — removes the
// STG.128 issue cost (~12 cyc each) from the LSU so DRAM can saturate.

#define PAIRS_PER_BLOCK 1024
#define BLOCK_THREADS   256

// SMEM float offsets (total 10240 floats = 40 KB)
#define S_FI   0
#define S_FJ   1024
#define S_FD   2048
#define S_FM   3072
#define S_RP   4096
#define S_RN   7168
#define S_TOT  10240

__device__ __forceinline__ float wrap_pbc(float x, float L, float h) {
    // matches jnp.remainder(x + h, L) - h  (floor-mod), L > 0
    float t = x + h;
    float m = fmodf(t, L);
    if (m < 0.0f) m += L;
    return m - h;
}

__device__ __forceinline__ uint32_t smem_u32(const void* p) {
    return (uint32_t)__cvta_generic_to_shared(p);
}

__device__ __forceinline__ void bulk_s2g(float* gdst, const float* ssrc, uint32_t bytes) {
    asm volatile(
        "cp.async.bulk.global.shared::cta.bulk_group [%0], [%1], %2;"
        :: "l"(gdst), "r"(smem_u32(ssrc)), "r"(bytes) : "memory");
}

__global__ void __launch_bounds__(BLOCK_THREADS)
nlist_kernel(const float* __restrict__ pos,
             const float* __restrict__ box,
             const int*   __restrict__ ip,
             const int*   __restrict__ jp,
             float*       __restrict__ out,
             int P)
{
    __shared__ float sm[S_TOT];

    const int t       = threadIdx.x;
    const int p_base  = blockIdx.x * PAIRS_PER_BLOCK;
    const size_t Ps   = (size_t)P;

    const float Lx = __ldg(box + 0);
    const float Ly = __ldg(box + 4);
    const float Lz = __ldg(box + 8);
    const float hx = 0.5f * Lx, hy = 0.5f * Ly, hz = 0.5f * Lz;
    const float CUTOFF = 0.5f;

    if (p_base + PAIRS_PER_BLOCK <= P) {
        // ================= fast path: full block of 1024 pairs =================
        const int p0 = p_base + t * 4;

        const int4 i4 = *(const int4*)(ip + p0);
        const int4 j4 = *(const int4*)(jp + p0);
        const int is[4] = {i4.x, i4.y, i4.z, i4.w};
        const int js[4] = {j4.x, j4.y, j4.z, j4.w};

        // pi gather; dedupe when all 4 pairs share the same row i (common case)
        float ax[4], ay[4], az[4];
        if (i4.x == i4.w) {
            const float* pi = pos + 3 * (size_t)i4.x;
            float x = __ldg(pi + 0), y = __ldg(pi + 1), z = __ldg(pi + 2);
            #pragma unroll
            for (int k = 0; k < 4; k++) { ax[k] = x; ay[k] = y; az[k] = z; }
        } else {
            #pragma unroll
            for (int k = 0; k < 4; k++) {
                const float* pi = pos + 3 * (size_t)is[k];
                ax[k] = __ldg(pi + 0); ay[k] = __ldg(pi + 1); az[k] = __ldg(pi + 2);
            }
        }

        float rx[4], ry[4], rz[4], dd[4], mk[4];
        #pragma unroll
        for (int k = 0; k < 4; k++) {
            const float* pj = pos + 3 * (size_t)js[k];
            float x = ax[k] - __ldg(pj + 0);
            float y = ay[k] - __ldg(pj + 1);
            float z = az[k] - __ldg(pj + 2);
            x = wrap_pbc(x, Lx, hx);
            y = wrap_pbc(y, Ly, hy);
            z = wrap_pbc(z, Lz, hz);
            float d = sqrtf(x * x + y * y + z * z);
            bool m = (d <= CUTOFF);
            rx[k] = m ? x : 0.0f;
            ry[k] = m ? y : 0.0f;
            rz[k] = m ? z : 0.0f;
            dd[k] = m ? d : 0.0f;
            mk[k] = m ? 1.0f : 0.0f;
        }

        // ---- stage into SMEM (unique regions only) ----
        *(float4*)(sm + S_FI + 4 * t) =
            make_float4((float)is[0], (float)is[1], (float)is[2], (float)is[3]);
        *(float4*)(sm + S_FJ + 4 * t) =
            make_float4((float)js[0], (float)js[1], (float)js[2], (float)js[3]);
        *(float4*)(sm + S_FD + 4 * t) = make_float4(dd[0], dd[1], dd[2], dd[3]);
        *(float4*)(sm + S_FM + 4 * t) = make_float4(mk[0], mk[1], mk[2], mk[3]);

        float* rp = sm + S_RP + 12 * t;
        *(float4*)(rp + 0) = make_float4(rx[0], ry[0], rz[0], rx[1]);
        *(float4*)(rp + 4) = make_float4(ry[1], rz[1], rx[2], ry[2]);
        *(float4*)(rp + 8) = make_float4(rz[2], rx[3], ry[3], rz[3]);

        float* rn = sm + S_RN + 12 * t;
        *(float4*)(rn + 0) = make_float4(-rx[0], -ry[0], -rz[0], -rx[1]);
        *(float4*)(rn + 4) = make_float4(-ry[1], -rz[1], -rx[2], -ry[2]);
        *(float4*)(rn + 8) = make_float4(-rz[2], -rx[3], -ry[3], -rz[3]);

        __syncthreads();

        // ---- one thread drains the block via bulk async copies ----
        if (t == 0) {
            asm volatile("fence.proxy.async.shared::cta;" ::: "memory");
            const uint32_t B1 = PAIRS_PER_BLOCK * 4;      // 4 KB
            const uint32_t B3 = 3 * PAIRS_PER_BLOCK * 4;  // 12 KB
            bulk_s2g(out +  0 * Ps + p_base,            sm + S_FI, B1);
            bulk_s2g(out +  3 * Ps + p_base,            sm + S_FI, B1);
            bulk_s2g(out +  1 * Ps + p_base,            sm + S_FJ, B1);
            bulk_s2g(out +  2 * Ps + p_base,            sm + S_FJ, B1);
            bulk_s2g(out +  4 * Ps + p_base,            sm + S_FD, B1);
            bulk_s2g(out +  5 * Ps + p_base,            sm + S_FD, B1);
            bulk_s2g(out + 12 * Ps + p_base,            sm + S_FM, B1);
            bulk_s2g(out + 13 * Ps + p_base,            sm + S_FM, B1);
            bulk_s2g(out +  6 * Ps + 3 * (size_t)p_base, sm + S_RP, B3);
            bulk_s2g(out +  9 * Ps + 3 * (size_t)p_base, sm + S_RN, B3);
            asm volatile("cp.async.bulk.commit_group;" ::: "memory");
            asm volatile("cp.async.bulk.wait_group 0;" ::: "memory");
        }
        // other threads may exit; block (and its SMEM) stays alive until t==0 finishes
    } else {
        // ================= tail path: partial block, direct stores =================
        for (int p = p_base + t; p < P; p += BLOCK_THREADS) {
            int i = __ldg(ip + p);
            int j = __ldg(jp + p);
            const float* pi = pos + 3 * (size_t)i;
            const float* pj = pos + 3 * (size_t)j;
            float x = __ldg(pi + 0) - __ldg(pj + 0);
            float y = __ldg(pi + 1) - __ldg(pj + 1);
            float z = __ldg(pi + 2) - __ldg(pj + 2);
            x = wrap_pbc(x, Lx, hx);
            y = wrap_pbc(y, Ly, hy);
            z = wrap_pbc(z, Lz, hz);
            float d = sqrtf(x * x + y * y + z * z);
            bool m = (d <= CUTOFF);
            float mx = m ? x : 0.0f, my = m ? y : 0.0f, mz = m ? z : 0.0f;
            float md = m ? d : 0.0f, mv = m ? 1.0f : 0.0f;

            out[ 0 * Ps + p] = (float)i;
            out[ 1 * Ps + p] = (float)j;
            out[ 2 * Ps + p] = (float)j;
            out[ 3 * Ps + p] = (float)i;
            out[ 4 * Ps + p] = md;
            out[ 5 * Ps + p] = md;
            out[ 6 * Ps + 3 * (size_t)p + 0] =  mx;
            out[ 6 * Ps + 3 * (size_t)p + 1] =  my;
            out[ 6 * Ps + 3 * (size_t)p + 2] =  mz;
            out[ 9 * Ps + 3 * (size_t)p + 0] = -mx;
            out[ 9 * Ps + 3 * (size_t)p + 1] = -my;
            out[ 9 * Ps + 3 * (size_t)p + 2] = -mz;
            out[12 * Ps + p] = mv;
            out[13 * Ps + p] = mv;
        }
    }
}

extern "C" void kernel_launch(void* const* d_in, const int* in_sizes, int n_in,
                              void* d_out, int out_size)
{
    const float* pos = (const float*)d_in[0];   // [N,3] float32
    const float* box = (const float*)d_in[1];   // [3,3] float32
    const int*   ip  = (const int*)d_in[2];     // [P] int32
    const int*   jp  = (const int*)d_in[3];     // [P] int32
    float* out = (float*)d_out;

    const int P = in_sizes[2];
    const int grid = (P + PAIRS_PER_BLOCK - 1) / PAIRS_PER_BLOCK;
    nlist_kernel<<<grid, BLOCK_THREADS>>>(pos, box, ip, jp, out, P);
}

// round 4
// speedup vs baseline: 1.1059x; 1.0308x over previous
#include <cuda_runtime.h>

// NeighborlistVerletNsq: all-pairs PBC displacement + cutoff mask.
// Output layout (float32, element offsets, P = N(N-1)/2 unique pairs):
//   [0P..1P)  i   [1P..2P) j   [2P..3P) j   [3P..4P) i
//   [4P..5P)  d   [5P..6P) d
//   [6P..9P)  r (row-major [P,3])   [9P..12P) -r
//   [12P..13P) mask  [13P..14P) mask

__device__ __forceinline__ float wrap_pbc(float x, float L, float h) {
    // floor-mod of (x+h) into [0,L), then -h. Valid (and bit-identical to
    // fmodf-based floor-mod) because t = x+h is always in (-L, 2L) here.
    float t = x + h;
    if (t >= L) t -= L;
    if (t < 0.0f) t += L;
    return t - h;
}

__global__ void __launch_bounds__(256, 6)
nlist_kernel(const float* __restrict__ pos,
             const float* __restrict__ box,
             const int*   __restrict__ ip,
             const int*   __restrict__ jp,
             float*       __restrict__ out,
             int P)
{
    const int t  = blockIdx.x * blockDim.x + threadIdx.x;
    const int p0 = t * 4;
    if (p0 >= P) return;

    const float Lx = __ldg(box + 0);
    const float Ly = __ldg(box + 4);
    const float Lz = __ldg(box + 8);
    const float hx = 0.5f * Lx, hy = 0.5f * Ly, hz = 0.5f * Lz;
    const float CUTOFF = 0.5f;

    const size_t Ps = (size_t)P;

    if (p0 + 3 < P) {
        // ---- vector path: 4 pairs per thread ----
        const int4 i4 = *(const int4*)(ip + p0);
        const int4 j4 = *(const int4*)(jp + p0);

        // Index regions depend only on the index loads: store them FIRST so
        // DRAM is busy while the position gathers are in flight.
        const float4 fi = make_float4((float)i4.x, (float)i4.y, (float)i4.z, (float)i4.w);
        const float4 fj = make_float4((float)j4.x, (float)j4.y, (float)j4.z, (float)j4.w);
        __stcs((float4*)(out + 0 * Ps + p0), fi);
        __stcs((float4*)(out + 1 * Ps + p0), fj);
        __stcs((float4*)(out + 2 * Ps + p0), fj);
        __stcs((float4*)(out + 3 * Ps + p0), fi);

        const int is[4] = {i4.x, i4.y, i4.z, i4.w};
        const int js[4] = {j4.x, j4.y, j4.z, j4.w};

        // pi gather; dedupe when all 4 pairs share row i (the common case)
        float ax[4], ay[4], az[4];
        if (i4.x == i4.w) {
            const float* pi = pos + 3 * (size_t)i4.x;
            float x = __ldg(pi + 0), y = __ldg(pi + 1), z = __ldg(pi + 2);
            #pragma unroll
            for (int k = 0; k < 4; k++) { ax[k] = x; ay[k] = y; az[k] = z; }
        } else {
            #pragma unroll
            for (int k = 0; k < 4; k++) {
                const float* pi = pos + 3 * (size_t)is[k];
                ax[k] = __ldg(pi + 0); ay[k] = __ldg(pi + 1); az[k] = __ldg(pi + 2);
            }
        }

        float rx[4], ry[4], rz[4], dd[4], mk[4];
        #pragma unroll
        for (int k = 0; k < 4; k++) {
            const float* pj = pos + 3 * (size_t)js[k];
            float x = ax[k] - __ldg(pj + 0);
            float y = ay[k] - __ldg(pj + 1);
            float z = az[k] - __ldg(pj + 2);
            x = wrap_pbc(x, Lx, hx);
            y = wrap_pbc(y, Ly, hy);
            z = wrap_pbc(z, Lz, hz);
            float d = sqrtf(x * x + y * y + z * z);
            bool m = (d <= CUTOFF);
            rx[k] = m ? x : 0.0f;
            ry[k] = m ? y : 0.0f;
            rz[k] = m ? z : 0.0f;
            dd[k] = m ? d : 0.0f;
            mk[k] = m ? 1.0f : 0.0f;
        }

        const float4 fd = make_float4(dd[0], dd[1], dd[2], dd[3]);
        const float4 fm = make_float4(mk[0], mk[1], mk[2], mk[3]);
        __stcs((float4*)(out + 4 * Ps + p0), fd);
        __stcs((float4*)(out + 5 * Ps + p0), fd);

        float* rpos = out + 6 * Ps + 3 * (size_t)p0;
        __stcs((float4*)(rpos + 0), make_float4(rx[0], ry[0], rz[0], rx[1]));
        __stcs((float4*)(rpos + 4), make_float4(ry[1], rz[1], rx[2], ry[2]));
        __stcs((float4*)(rpos + 8), make_float4(rz[2], rx[3], ry[3], rz[3]));

        float* rneg = out + 9 * Ps + 3 * (size_t)p0;
        __stcs((float4*)(rneg + 0), make_float4(-rx[0], -ry[0], -rz[0], -rx[1]));
        __stcs((float4*)(rneg + 4), make_float4(-ry[1], -rz[1], -rx[2], -ry[2]));
        __stcs((float4*)(rneg + 8), make_float4(-rz[2], -rx[3], -ry[3], -rz[3]));

        __stcs((float4*)(out + 12 * Ps + p0), fm);
        __stcs((float4*)(out + 13 * Ps + p0), fm);
    } else {
        // ---- scalar tail ----
        for (int p = p0; p < P; p++) {
            int i = __ldg(ip + p);
            int j = __ldg(jp + p);
            const float* pi = pos + 3 * (size_t)i;
            const float* pj = pos + 3 * (size_t)j;
            float x = __ldg(pi + 0) - __ldg(pj + 0);
            float y = __ldg(pi + 1) - __ldg(pj + 1);
            float z = __ldg(pi + 2) - __ldg(pj + 2);
            x = wrap_pbc(x, Lx, hx);
            y = wrap_pbc(y, Ly, hy);
            z = wrap_pbc(z, Lz, hz);
            float d = sqrtf(x * x + y * y + z * z);
            bool m = (d <= CUTOFF);
            float mx = m ? x : 0.0f, my = m ? y : 0.0f, mz = m ? z : 0.0f;
            float md = m ? d : 0.0f, mv = m ? 1.0f : 0.0f;

            out[ 0 * Ps + p] = (float)i;
            out[ 1 * Ps + p] = (float)j;
            out[ 2 * Ps + p] = (float)j;
            out[ 3 * Ps + p] = (float)i;
            out[ 4 * Ps + p] = md;
            out[ 5 * Ps + p] = md;
            out[ 6 * Ps + 3 * (size_t)p + 0] =  mx;
            out[ 6 * Ps + 3 * (size_t)p + 1] =  my;
            out[ 6 * Ps + 3 * (size_t)p + 2] =  mz;
            out[ 9 * Ps + 3 * (size_t)p + 0] = -mx;
            out[ 9 * Ps + 3 * (size_t)p + 1] = -my;
            out[ 9 * Ps + 3 * (size_t)p + 2] = -mz;
            out[12 * Ps + p] = mv;
            out[13 * Ps + p] = mv;
        }
    }
}

extern "C" void kernel_launch(void* const* d_in, const int* in_sizes, int n_in,
                              void* d_out, int out_size)
{
    const float* pos = (const float*)d_in[0];   // [N,3] float32
    const float* box = (const float*)d_in[1];   // [3,3] float32
    const int*   ip  = (const int*)d_in[2];     // [P] int32
    const int*   jp  = (const int*)d_in[3];     // [P] int32
    float* out = (float*)d_out;

    const int P = in_sizes[2];
    const int nthreads = (P + 3) / 4;
    const int block = 256;
    const int grid = (nthreads + block - 1) / block;
    nlist_kernel<<<grid, block>>>(pos, box, ip, jp, out, P);
}

// round 5
// speedup vs baseline: 1.2986x; 1.1743x over previous
#include <cuda_runtime.h>

// NeighborlistVerletNsq: all-pairs PBC displacement + cutoff mask.
// Output layout (float32, element offsets, P = N(N-1)/2 unique pairs):
//   [0P..1P)  i   [1P..2P) j   [2P..3P) j   [3P..4P) i
//   [4P..5P)  d   [5P..6P) d
//   [6P..9P)  r (row-major [P,3])   [9P..12P) -r
//   [12P..13P) mask  [13P..14P) mask
//
// i/j reconstructed analytically from the flat pair index (triu_indices is
// closed-form): removes 67 MB of DRAM reads -> pure write stream.

__device__ __forceinline__ float wrap_pbc(float x, float L, float h) {
    // floor-mod of (x+h) into [0,L), then -h. Valid because t=x+h is in (-L,2L).
    float t = x + h;
    if (t >= L) t -= L;
    if (t < 0.0f) t += L;
    return t - h;
}

// start offset of row i in the triu(k=1) enumeration: S(i) = i*(2N-1-i)/2
__device__ __forceinline__ int row_start(int i, int N) {
    return (i * (2 * N - 1 - i)) >> 1;
}

// exact row index i such that row_start(i) <= p < row_start(i+1)
__device__ __forceinline__ int row_of(int p, int N) {
    const float A = (float)(2 * N - 1);
    float disc = A * A - 8.0f * (float)p;          // <= (2N-1)^2 ~ 6.7e7
    int i = (int)((A - sqrtf(disc)) * 0.5f);       // off by at most 1
    i = min(max(i, 0), N - 2);
    if (p >= row_start(i + 1, N) && i < N - 2) ++i;
    else if (p < row_start(i, N)) --i;
    return i;
}

__global__ void __launch_bounds__(256, 5)
nlist_kernel(const float* __restrict__ pos,
             const float* __restrict__ box,
             float*       __restrict__ out,
             int P, int N)
{
    const int t  = blockIdx.x * blockDim.x + threadIdx.x;
    const int p0 = t * 4;
    if (p0 >= P) return;

    const float Lx = __ldg(box + 0);
    const float Ly = __ldg(box + 4);
    const float Lz = __ldg(box + 8);
    const float hx = 0.5f * Lx, hy = 0.5f * Ly, hz = 0.5f * Lz;
    const float CUTOFF = 0.5f;
    const size_t Ps = (size_t)P;

    if (p0 + 3 < P) {
        // ---- recover (i, j) for the 4 consecutive pairs ----
        int i = row_of(p0, N);
        int j = i + 1 + (p0 - row_start(i, N));

        int is[4], js[4];
        #pragma unroll
        for (int k = 0; k < 4; k++) {
            is[k] = i; js[k] = j;
            ++j;
            if (j >= N) { ++i; j = i + 1; }
        }

        // Index regions first: DRAM busy while position gathers are in flight.
        const float4 fi = make_float4((float)is[0], (float)is[1], (float)is[2], (float)is[3]);
        const float4 fj = make_float4((float)js[0], (float)js[1], (float)js[2], (float)js[3]);
        __stcs((float4*)(out + 0 * Ps + p0), fi);
        __stcs((float4*)(out + 1 * Ps + p0), fj);
        __stcs((float4*)(out + 2 * Ps + p0), fj);
        __stcs((float4*)(out + 3 * Ps + p0), fi);

        // pi gather; dedupe when all 4 pairs share row i (the common case)
        float ax[4], ay[4], az[4];
        if (is[0] == is[3]) {
            const float* pi = pos + 3 * (size_t)is[0];
            float x = __ldg(pi + 0), y = __ldg(pi + 1), z = __ldg(pi + 2);
            #pragma unroll
            for (int k = 0; k < 4; k++) { ax[k] = x; ay[k] = y; az[k] = z; }
        } else {
            #pragma unroll
            for (int k = 0; k < 4; k++) {
                const float* pi = pos + 3 * (size_t)is[k];
                ax[k] = __ldg(pi + 0); ay[k] = __ldg(pi + 1); az[k] = __ldg(pi + 2);
            }
        }

        float rx[4], ry[4], rz[4], dd[4], mk[4];
        #pragma unroll
        for (int k = 0; k < 4; k++) {
            const float* pj = pos + 3 * (size_t)js[k];
            float x = ax[k] - __ldg(pj + 0);
            float y = ay[k] - __ldg(pj + 1);
            float z = az[k] - __ldg(pj + 2);
            x = wrap_pbc(x, Lx, hx);
            y = wrap_pbc(y, Ly, hy);
            z = wrap_pbc(z, Lz, hz);
            float d = sqrtf(x * x + y * y + z * z);
            bool m = (d <= CUTOFF);
            rx[k] = m ? x : 0.0f;
            ry[k] = m ? y : 0.0f;
            rz[k] = m ? z : 0.0f;
            dd[k] = m ? d : 0.0f;
            mk[k] = m ? 1.0f : 0.0f;
        }

        const float4 fd = make_float4(dd[0], dd[1], dd[2], dd[3]);
        const float4 fm = make_float4(mk[0], mk[1], mk[2], mk[3]);
        __stcs((float4*)(out + 4 * Ps + p0), fd);
        __stcs((float4*)(out + 5 * Ps + p0), fd);

        float* rpos = out + 6 * Ps + 3 * (size_t)p0;
        __stcs((float4*)(rpos + 0), make_float4(rx[0], ry[0], rz[0], rx[1]));
        __stcs((float4*)(rpos + 4), make_float4(ry[1], rz[1], rx[2], ry[2]));
        __stcs((float4*)(rpos + 8), make_float4(rz[2], rx[3], ry[3], rz[3]));

        float* rneg = out + 9 * Ps + 3 * (size_t)p0;
        __stcs((float4*)(rneg + 0), make_float4(-rx[0], -ry[0], -rz[0], -rx[1]));
        __stcs((float4*)(rneg + 4), make_float4(-ry[1], -rz[1], -rx[2], -ry[2]));
        __stcs((float4*)(rneg + 8), make_float4(-rz[2], -rx[3], -ry[3], -rz[3]));

        __stcs((float4*)(out + 12 * Ps + p0), fm);
        __stcs((float4*)(out + 13 * Ps + p0), fm);
    } else {
        // ---- scalar tail ----
        for (int p = p0; p < P; p++) {
            int i = row_of(p, N);
            int j = i + 1 + (p - row_start(i, N));
            const float* pi = pos + 3 * (size_t)i;
            const float* pj = pos + 3 * (size_t)j;
            float x = __ldg(pi + 0) - __ldg(pj + 0);
            float y = __ldg(pi + 1) - __ldg(pj + 1);
            float z = __ldg(pi + 2) - __ldg(pj + 2);
            x = wrap_pbc(x, Lx, hx);
            y = wrap_pbc(y, Ly, hy);
            z = wrap_pbc(z, Lz, hz);
            float d = sqrtf(x * x + y * y + z * z);
            bool m = (d <= CUTOFF);
            float mx = m ? x : 0.0f, my = m ? y : 0.0f, mz = m ? z : 0.0f;
            float md = m ? d : 0.0f, mv = m ? 1.0f : 0.0f;

            out[ 0 * Ps + p] = (float)i;
            out[ 1 * Ps + p] = (float)j;
            out[ 2 * Ps + p] = (float)j;
            out[ 3 * Ps + p] = (float)i;
            out[ 4 * Ps + p] = md;
            out[ 5 * Ps + p] = md;
            out[ 6 * Ps + 3 * (size_t)p + 0] =  mx;
            out[ 6 * Ps + 3 * (size_t)p + 1] =  my;
            out[ 6 * Ps + 3 * (size_t)p + 2] =  mz;
            out[ 9 * Ps + 3 * (size_t)p + 0] = -mx;
            out[ 9 * Ps + 3 * (size_t)p + 1] = -my;
            out[ 9 * Ps + 3 * (size_t)p + 2] = -mz;
            out[12 * Ps + p] = mv;
            out[13 * Ps + p] = mv;
        }
    }
}

extern "C" void kernel_launch(void* const* d_in, const int* in_sizes, int n_in,
                              void* d_out, int out_size)
{
    const float* pos = (const float*)d_in[0];   // [N,3] float32
    const float* box = (const float*)d_in[1];   // [3,3] float32
    // d_in[2]/d_in[3] (i_pairs/j_pairs) reconstructed analytically — not read.
    float* out = (float*)d_out;

    const int P = in_sizes[2];
    const int N = in_sizes[0] / 3;
    const int nthreads = (P + 3) / 4;
    const int block = 256;
    const int grid = (nthreads + block - 1) / block;
    nlist_kernel<<<grid, block>>>(pos, box, out, P, N);
}